// round 6
// baseline (speedup 1.0000x reference)
#include <cuda_runtime.h>

// FAC (per-pixel dynamic 3x3 filter) + LeakyReLU(0.2)
// feature: [N=8, C=64, H=128, W=128] f32
// filters: [N, C*9, H, W] f32, tap index = kh*3+kw minor within channel-major C
//
// DRAM traffic is at the 335 MB floor (filters 302 + out 33.5; feature is
// L2-resident). R6 vs R5: each thread computes TWO output rows (h, h+1),
// sharing the 4 feature rows h-1..h+2 and issuing 18 back-to-back filter
// ldcs4 loads -> 2x per-thread MLP on the DRAM-binding stream for better
// bus efficiency (goal: 85.4% -> ~88%).

#define HW 16384      // 128*128
#define W  128
#define H  128

__device__ __forceinline__ float4 ldcs4(const float* p) {
    float4 v;
    asm volatile("ld.global.cs.v4.f32 {%0,%1,%2,%3}, [%4];"
                 : "=f"(v.x), "=f"(v.y), "=f"(v.z), "=f"(v.w)
                 : "l"(p));
    return v;
}

__device__ __forceinline__ void stcs4(float* p, float4 v) {
    asm volatile("st.global.cs.v4.f32 [%0], {%1,%2,%3,%4};"
                 :: "l"(p), "f"(v.x), "f"(v.y), "f"(v.z), "f"(v.w)
                 : "memory");
}

// one kh row: 3 filter taps (kw=0..2) against window (f0 | m | f5)
__device__ __forceinline__ void acc_row(const float* tap,
                                        float f0, float4 m, float f5,
                                        float& a0, float& a1, float& a2, float& a3)
{
    float4 t0 = ldcs4(tap);
    a0 = fmaf(t0.x, f0,  a0);
    a1 = fmaf(t0.y, m.x, a1);
    a2 = fmaf(t0.z, m.y, a2);
    a3 = fmaf(t0.w, m.z, a3);
    float4 t1 = ldcs4(tap + HW);
    a0 = fmaf(t1.x, m.x, a0);
    a1 = fmaf(t1.y, m.y, a1);
    a2 = fmaf(t1.z, m.z, a2);
    a3 = fmaf(t1.w, m.w, a3);
    float4 t2 = ldcs4(tap + 2 * HW);
    a0 = fmaf(t2.x, m.y, a0);
    a1 = fmaf(t2.y, m.z, a1);
    a2 = fmaf(t2.z, m.w, a2);
    a3 = fmaf(t2.w, f5,  a3);
}

__device__ __forceinline__ float4 leaky4(float a0, float a1, float a2, float a3)
{
    float4 o;
    o.x = a0 >= 0.f ? a0 : 0.2f * a0;
    o.y = a1 >= 0.f ? a1 : 0.2f * a1;
    o.z = a2 >= 0.f ? a2 : 0.2f * a2;
    o.w = a3 >= 0.f ? a3 : 0.2f * a3;
    return o;
}

__global__ __launch_bounds__(256)
void fac_leaky_kernel(const float* __restrict__ feat,
                      const float* __restrict__ filt,
                      float* __restrict__ out)
{
    // vec index over N*C*(H/2)*(W/4) = 1,048,576 ; lane == wv (warp spans a row)
    int idx = blockIdx.x * blockDim.x + threadIdx.x;

    int lane = idx & 31;            // W/4 group
    int hp   = (idx >> 5) & 63;     // row pair
    int nc   = idx >> 11;           // n*64 + c
    int h0   = hp << 1;             // even row
    int w0   = lane << 2;

    const float* fb  = feat + (size_t)nc * HW;
    const float* pb0 = filt + (size_t)nc * 9 * HW + h0 * W + w0;   // taps, row h0
    const float* pb1 = pb0 + W;                                    // taps, row h0+1

    // 4 feature rows: h0-1 .. h0+2 (zero-padded at image edges)
    float4 m[4];
    float  f0[4], f5[4];
    #pragma unroll
    for (int r = 0; r < 4; ++r) {
        int hh = h0 - 1 + r;
        if (hh >= 0 && hh < H) {
            m[r] = *reinterpret_cast<const float4*>(fb + hh * W + w0);
        } else {
            m[r] = make_float4(0.f, 0.f, 0.f, 0.f);
        }
        f0[r] = __shfl_up_sync(0xffffffffu,   m[r].w, 1);
        f5[r] = __shfl_down_sync(0xffffffffu, m[r].x, 1);
        if (lane == 0)  f0[r] = 0.f;
        if (lane == 31) f5[r] = 0.f;
    }

    float a0 = 0.f, a1 = 0.f, a2 = 0.f, a3 = 0.f;   // output row h0
    float b0 = 0.f, b1 = 0.f, b2 = 0.f, b3 = 0.f;   // output row h0+1

    #pragma unroll
    for (int kh = 0; kh < 3; ++kh) {
        acc_row(pb0 + kh * 3 * HW, f0[kh],     m[kh],     f5[kh],     a0, a1, a2, a3);
        acc_row(pb1 + kh * 3 * HW, f0[kh + 1], m[kh + 1], f5[kh + 1], b0, b1, b2, b3);
    }

    float* ob = out + (size_t)nc * HW + h0 * W + w0;
    stcs4(ob,     leaky4(a0, a1, a2, a3));
    stcs4(ob + W, leaky4(b0, b1, b2, b3));
}

extern "C" void kernel_launch(void* const* d_in, const int* in_sizes, int n_in,
                              void* d_out, int out_size)
{
    const float* feature = (const float*)d_in[0];   // 8*64*128*128
    const float* filters = (const float*)d_in[1];   // 8*576*128*128
    float* out = (float*)d_out;

    // threads: N*C*(H/2)*(W/4) = 1,048,576
    const int total = 8 * 64 * (128 / 2) * (128 / 4);
    const int threads = 256;
    const int blocks = total / threads;             // 4096

    fac_leaky_kernel<<<blocks, threads>>>(feature, filters, out);
}

// round 9
// speedup vs baseline: 1.0868x; 1.0868x over previous
#include <cuda_runtime.h>

// FAC (per-pixel dynamic 3x3 filter) + LeakyReLU(0.2)
// feature: [8,64,128,128] f32; filters: [8,576,128,128] f32 (tap kh*3+kw minor)
//
// DRAM-bound at the 335 MB floor (filters 302 MB read-once + out 33.5 MB;
// feature is L2-resident). R7 = R5 structure (one row/thread, 2M threads,
// shuffle halo, ldcs/stcs) + one change: __launch_bounds__(256,6) gives
// ptxas a 42-reg budget so the 3 filter-tap loads per kh row batch up
// front (per-thread MLP ~6 on the DRAM stream) at 75% occupancy.
// Goal: chip-wide outstanding requests 34K -> 42K, DRAM% 85.4 -> ~88.

#define HW 16384      // 128*128
#define W  128
#define H  128

__device__ __forceinline__ float4 ldcs4(const float* p) {
    float4 v;
    asm volatile("ld.global.cs.v4.f32 {%0,%1,%2,%3}, [%4];"
                 : "=f"(v.x), "=f"(v.y), "=f"(v.z), "=f"(v.w)
                 : "l"(p));
    return v;
}

__device__ __forceinline__ void stcs4(float* p, float4 v) {
    asm volatile("st.global.cs.v4.f32 [%0], {%1,%2,%3,%4};"
                 :: "l"(p), "f"(v.x), "f"(v.y), "f"(v.z), "f"(v.w)
                 : "memory");
}

__global__ __launch_bounds__(256, 6)
void fac_leaky_kernel(const float* __restrict__ feat,
                      const float* __restrict__ filt,
                      float* __restrict__ out)
{
    // vec index over N*C*H*(W/4) = 2,097,152 ; lane == wv (warp spans one row)
    int idx = blockIdx.x * blockDim.x + threadIdx.x;

    int lane = idx & 31;            // W/4 group
    int h  = (idx >> 5) & 127;
    int nc = idx >> 12;             // n*64 + c
    int w0 = lane << 2;

    const float* fb = feat + (size_t)nc * HW;
    const float* pb = filt + (size_t)nc * 9 * HW + h * W + w0;

    float acc0 = 0.f, acc1 = 0.f, acc2 = 0.f, acc3 = 0.f;

    #pragma unroll
    for (int kh = 0; kh < 3; ++kh) {
        // batch the 3 tap loads for this kh row (DRAM-binding stream) first
        const float* tap = pb + kh * 3 * HW;
        float4 t0 = ldcs4(tap);
        float4 t1 = ldcs4(tap + HW);
        float4 t2 = ldcs4(tap + 2 * HW);

        int hh = h + kh - 1;
        float4 mid;
        if (hh >= 0 && hh < H) {
            mid = *reinterpret_cast<const float4*>(fb + hh * W + w0);
        } else {
            mid = make_float4(0.f, 0.f, 0.f, 0.f);
        }
        float f0 = __shfl_up_sync(0xffffffffu,   mid.w, 1);
        float f5 = __shfl_down_sync(0xffffffffu, mid.x, 1);
        if (lane == 0)  f0 = 0.f;
        if (lane == 31) f5 = 0.f;

        // kw = 0 : window offset [0..3]
        acc0 = fmaf(t0.x, f0,    acc0);
        acc1 = fmaf(t0.y, mid.x, acc1);
        acc2 = fmaf(t0.z, mid.y, acc2);
        acc3 = fmaf(t0.w, mid.z, acc3);
        // kw = 1 : offset [1..4]
        acc0 = fmaf(t1.x, mid.x, acc0);
        acc1 = fmaf(t1.y, mid.y, acc1);
        acc2 = fmaf(t1.z, mid.z, acc2);
        acc3 = fmaf(t1.w, mid.w, acc3);
        // kw = 2 : offset [2..5]
        acc0 = fmaf(t2.x, mid.y, acc0);
        acc1 = fmaf(t2.y, mid.z, acc1);
        acc2 = fmaf(t2.z, mid.w, acc2);
        acc3 = fmaf(t2.w, f5,    acc3);
    }

    float4 o;
    o.x = acc0 >= 0.f ? acc0 : 0.2f * acc0;
    o.y = acc1 >= 0.f ? acc1 : 0.2f * acc1;
    o.z = acc2 >= 0.f ? acc2 : 0.2f * acc2;
    o.w = acc3 >= 0.f ? acc3 : 0.2f * acc3;

    stcs4(out + (size_t)nc * HW + h * W + w0, o);
}

extern "C" void kernel_launch(void* const* d_in, const int* in_sizes, int n_in,
                              void* d_out, int out_size)
{
    const float* feature = (const float*)d_in[0];   // 8*64*128*128
    const float* filters = (const float*)d_in[1];   // 8*576*128*128
    float* out = (float*)d_out;

    const int total_vec = 8 * 64 * 128 * (128 / 4); // 2,097,152
    const int threads = 256;
    const int blocks = total_vec / threads;         // 8192

    fac_leaky_kernel<<<blocks, threads>>>(feature, filters, out);
}